// round 1
// baseline (speedup 1.0000x reference)
#include <cuda_runtime.h>
#include <cuda_bf16.h>
#include <math.h>

#define N_ 4096
#define F_ 512

// Scratch (allocation-free requirement -> __device__ globals)
__device__ float g_D[(size_t)N_ * N_];   // 64 MB distance matrix
__device__ float g_negsum[N_];
__device__ float g_a2[N_];
__device__ float g_b2[N_];
__device__ double g_sum;
__device__ unsigned long long g_npos;

__global__ void init_kernel() {
    int i = blockIdx.x * blockDim.x + threadIdx.x;
    if (i < N_) g_negsum[i] = 0.0f;
    if (i == 0) { g_sum = 0.0; g_npos = 0ull; }
}

// blockIdx.x in [0, 2N): first N blocks -> rows of a, next N -> rows of b
__global__ void norms_kernel(const float* __restrict__ a, const float* __restrict__ b) {
    int row = blockIdx.x & (N_ - 1);
    const float* m = (blockIdx.x < N_) ? a : b;
    float* outp = (blockIdx.x < N_) ? g_a2 : g_b2;
    const float* p = m + (size_t)row * F_;
    float s = 0.0f;
    for (int k = threadIdx.x; k < F_; k += blockDim.x) {
        float v = p[k];
        s += v * v;
    }
    #pragma unroll
    for (int o = 16; o; o >>= 1) s += __shfl_xor_sync(0xffffffffu, s, o);
    __shared__ float ws[32];
    int lane = threadIdx.x & 31, w = threadIdx.x >> 5;
    if (lane == 0) ws[w] = s;
    __syncthreads();
    if (threadIdx.x == 0) {
        float t = 0.0f;
        int nw = blockDim.x >> 5;
        for (int i = 0; i < nw; ++i) t += ws[i];
        outp[row] = t;
    }
}

// Fused pairwise-distance GEMM: D[i,j] = sqrt(max(|b_i|^2+|a_j|^2-2 b_i.a_j, 0))
// Also accumulates row_negsum[i] = sum_{labels[j]!=labels[i]} exp(1 - D[i,j]).
// 128x128 block tile, BK=16, 256 threads, 8x8 per thread.
__global__ __launch_bounds__(256, 2)
void dist_kernel(const float* __restrict__ a, const float* __restrict__ b,
                 const int* __restrict__ labels) {
    __shared__ float Bt[16][132];   // [k][m]  (b rows -> i)
    __shared__ float At[16][132];   // [k][n]  (a rows -> j)

    const int tid = threadIdx.x;
    const int bi0 = blockIdx.y * 128;   // i tile base (b rows)
    const int aj0 = blockIdx.x * 128;   // j tile base (a rows)
    const int m0 = (tid >> 4) << 3;     // 0..120
    const int n0 = (tid & 15) << 3;     // 0..120

    float acc[8][8];
    #pragma unroll
    for (int i = 0; i < 8; ++i)
        #pragma unroll
        for (int j = 0; j < 8; ++j) acc[i][j] = 0.0f;

    for (int k0 = 0; k0 < F_; k0 += 16) {
        // load 128x16 tiles of b and a (transposed into smem)
        #pragma unroll
        for (int l = 0; l < 2; ++l) {
            int f = tid + l * 256;        // float4 index 0..511
            int row = f >> 2;             // 0..127
            int kq = (f & 3) << 2;        // 0,4,8,12
            float4 vb = *(const float4*)(b + (size_t)(bi0 + row) * F_ + k0 + kq);
            Bt[kq + 0][row] = vb.x; Bt[kq + 1][row] = vb.y;
            Bt[kq + 2][row] = vb.z; Bt[kq + 3][row] = vb.w;
            float4 va = *(const float4*)(a + (size_t)(aj0 + row) * F_ + k0 + kq);
            At[kq + 0][row] = va.x; At[kq + 1][row] = va.y;
            At[kq + 2][row] = va.z; At[kq + 3][row] = va.w;
        }
        __syncthreads();

        #pragma unroll
        for (int k = 0; k < 16; ++k) {
            float rB[8], rA[8];
            #pragma unroll
            for (int x = 0; x < 8; ++x) { rB[x] = Bt[k][m0 + x]; rA[x] = At[k][n0 + x]; }
            #pragma unroll
            for (int i = 0; i < 8; ++i)
                #pragma unroll
                for (int j = 0; j < 8; ++j)
                    acc[i][j] = fmaf(rB[i], rA[j], acc[i][j]);
        }
        __syncthreads();
    }

    // Epilogue: distances, D store, masked exp row-accumulation
    float b2r[8], a2c[8];
    int lb[8], la[8];
    #pragma unroll
    for (int x = 0; x < 8; ++x) {
        int gi = bi0 + m0 + x;
        int gj = aj0 + n0 + x;
        b2r[x] = g_b2[gi]; lb[x] = labels[gi];
        a2c[x] = g_a2[gj]; la[x] = labels[gj];
    }

    float negacc[8];
    #pragma unroll
    for (int i = 0; i < 8; ++i) negacc[i] = 0.0f;

    #pragma unroll
    for (int i = 0; i < 8; ++i) {
        int gi = bi0 + m0 + i;
        float dv[8];
        #pragma unroll
        for (int j = 0; j < 8; ++j) {
            float dsq = b2r[i] + a2c[j] - 2.0f * acc[i][j];
            float d = sqrtf(fmaxf(dsq, 0.0f));
            dv[j] = d;
            if (lb[i] != la[j]) negacc[i] += expf(1.0f - d);
        }
        float4* dst = (float4*)(g_D + (size_t)gi * N_ + aj0 + n0);
        dst[0] = make_float4(dv[0], dv[1], dv[2], dv[3]);
        dst[1] = make_float4(dv[4], dv[5], dv[6], dv[7]);
    }

    // Reduce negacc across the 16 lanes that share the same 8 rows
    // (tid = ty*16 + tx; a 16-lane half-warp == one ty)
    #pragma unroll
    for (int i = 0; i < 8; ++i) {
        float v = negacc[i];
        #pragma unroll
        for (int o = 8; o; o >>= 1) v += __shfl_xor_sync(0xffffffffu, v, o);
        if ((tid & 15) == 0) atomicAdd(&g_negsum[bi0 + m0 + i], v);
    }
}

// One block per row i: sum over positive pairs of max(log(ns_i+ns_j)+D, 0)^2
__global__ void loss_kernel(const int* __restrict__ labels) {
    int i = blockIdx.x;
    int li = labels[i];
    float nsi = g_negsum[i];
    const float* Drow = g_D + (size_t)i * N_;

    float acc = 0.0f;
    unsigned cnt = 0;
    for (int j = threadIdx.x; j < N_; j += blockDim.x) {
        if (labels[j] == li && j != i) {
            float Jv = logf(nsi + g_negsum[j]) + Drow[j];
            float h = fmaxf(Jv, 0.0f);
            acc += h * h;
            cnt++;
        }
    }
    #pragma unroll
    for (int o = 16; o; o >>= 1) {
        acc += __shfl_xor_sync(0xffffffffu, acc, o);
        cnt += __shfl_xor_sync(0xffffffffu, cnt, o);
    }
    __shared__ float fs[32];
    __shared__ unsigned cs[32];
    int lane = threadIdx.x & 31, w = threadIdx.x >> 5;
    if (lane == 0) { fs[w] = acc; cs[w] = cnt; }
    __syncthreads();
    if (threadIdx.x == 0) {
        float t = 0.0f;
        unsigned c = 0;
        int nw = blockDim.x >> 5;
        for (int k = 0; k < nw; ++k) { t += fs[k]; c += cs[k]; }
        atomicAdd(&g_sum, (double)t);
        atomicAdd(&g_npos, (unsigned long long)c);
    }
}

__global__ void finalize_kernel(float* out) {
    out[0] = (float)(g_sum / (2.0 * (double)g_npos));
}

extern "C" void kernel_launch(void* const* d_in, const int* in_sizes, int n_in,
                              void* d_out, int out_size) {
    const float* a = (const float*)d_in[0];
    const float* b = (const float*)d_in[1];
    const int* labels = (const int*)d_in[2];
    float* out = (float*)d_out;

    init_kernel<<<(N_ + 255) / 256, 256>>>();
    norms_kernel<<<2 * N_, 128>>>(a, b);
    dim3 grid(N_ / 128, N_ / 128);
    dist_kernel<<<grid, 256>>>(a, b, labels);
    loss_kernel<<<N_, 256>>>(labels);
    finalize_kernel<<<1, 1>>>(out);
}

// round 4
// speedup vs baseline: 1.6865x; 1.6865x over previous
#include <cuda_runtime.h>
#include <cuda_bf16.h>
#include <cstdint>
#include <math.h>

#define N_ 4096
#define F_ 512
#define TM 128
#define TNJ 128
#define BK 64
#define NSTAGE (F_ / BK)        // 8
#define TILE_BYTES 16384        // 128 rows x 128B
#define STAGE_BYTES (4 * TILE_BYTES)   // Bh, Bl, Ah, Al
#define SMEM_TOTAL (2 * STAGE_BYTES)   // 131072

// ---------------- scratch (__device__ globals; no allocs allowed) ----------------
__device__ float g_D[(size_t)N_ * N_];                       // 64 MB distances
__device__ __align__(16) __nv_bfloat16 g_ahi[(size_t)N_ * F_];
__device__ __align__(16) __nv_bfloat16 g_alo[(size_t)N_ * F_];
__device__ __align__(16) __nv_bfloat16 g_bhi[(size_t)N_ * F_];
__device__ __align__(16) __nv_bfloat16 g_blo[(size_t)N_ * F_];
__device__ float g_negsum[N_];
__device__ float g_a2[N_], g_b2[N_];
__device__ int   g_cnt[16];
__device__ int   g_group[16 * N_];
__device__ double g_sum;

// ---------------- helpers ----------------
__device__ __forceinline__ uint32_t smem_u32(const void* p) {
    uint32_t r;
    asm("{ .reg .u64 t; cvta.to.shared.u64 t, %1; cvt.u32.u64 %0, t; }" : "=r"(r) : "l"(p));
    return r;
}

#define LDSM4(r, addr) \
    asm volatile("ldmatrix.sync.aligned.m8n8.x4.shared.b16 {%0,%1,%2,%3}, [%4];" \
                 : "=r"((r)[0]), "=r"((r)[1]), "=r"((r)[2]), "=r"((r)[3]) : "r"(addr))

#define MMA16816(d, a, b0, b1) \
    asm volatile("mma.sync.aligned.m16n8k16.row.col.f32.bf16.bf16.f32 " \
                 "{%0,%1,%2,%3}, {%4,%5,%6,%7}, {%8,%9}, {%0,%1,%2,%3};" \
                 : "+f"((d)[0]), "+f"((d)[1]), "+f"((d)[2]), "+f"((d)[3]) \
                 : "r"((a)[0]), "r"((a)[1]), "r"((a)[2]), "r"((a)[3]), "r"(b0), "r"(b1))

#define CP_ASYNC16(saddr, gptr) \
    asm volatile("cp.async.cg.shared.global [%0], [%1], 16;" :: "r"(saddr), "l"(gptr))
#define CP_COMMIT() asm volatile("cp.async.commit_group;" ::: "memory")
#define CP_WAIT1()  asm volatile("cp.async.wait_group 1;" ::: "memory")
#define CP_WAIT0()  asm volatile("cp.async.wait_group 0;" ::: "memory")

// ---------------- small kernels ----------------
__global__ void init_kernel() {
    int i = blockIdx.x * blockDim.x + threadIdx.x;
    if (i < N_) g_negsum[i] = 0.0f;
    if (i < 16) g_cnt[i] = 0;
    if (i == 0) g_sum = 0.0;
}

// split fp32 -> bf16 hi/lo for both matrices
__global__ void convert_kernel(const float* __restrict__ a, const float* __restrict__ b) {
    const int PER = N_ * F_ / 4;
    int idx = blockIdx.x * blockDim.x + threadIdx.x;
    const float* src;
    __nv_bfloat16 *dh, *dl;
    int e;
    if (idx < PER) { src = a; dh = g_ahi; dl = g_alo; e = idx; }
    else           { src = b; dh = g_bhi; dl = g_blo; e = idx - PER; }
    float4 v = ((const float4*)src)[e];
    float vs[4] = {v.x, v.y, v.z, v.w};
    unsigned short h[4], l[4];
#pragma unroll
    for (int q = 0; q < 4; ++q) {
        __nv_bfloat16 hb = __float2bfloat16(vs[q]);
        __nv_bfloat16 lb = __float2bfloat16(vs[q] - __bfloat162float(hb));
        h[q] = __bfloat16_as_ushort(hb);
        l[q] = __bfloat16_as_ushort(lb);
    }
    uint2 ph = make_uint2(((uint32_t)h[1] << 16) | h[0], ((uint32_t)h[3] << 16) | h[2]);
    uint2 pl = make_uint2(((uint32_t)l[1] << 16) | l[0], ((uint32_t)l[3] << 16) | l[2]);
    ((uint2*)dh)[e] = ph;
    ((uint2*)dl)[e] = pl;
}

__global__ void norms_kernel(const float* __restrict__ a, const float* __restrict__ b) {
    int row = blockIdx.x & (N_ - 1);
    const float* m = (blockIdx.x < N_) ? a : b;
    float* outp = (blockIdx.x < N_) ? g_a2 : g_b2;
    const float* p = m + (size_t)row * F_;
    float s = 0.0f;
    for (int k = threadIdx.x; k < F_; k += blockDim.x) { float v = p[k]; s += v * v; }
#pragma unroll
    for (int o = 16; o; o >>= 1) s += __shfl_xor_sync(0xffffffffu, s, o);
    __shared__ float ws[4];
    int lane = threadIdx.x & 31, w = threadIdx.x >> 5;
    if (lane == 0) ws[w] = s;
    __syncthreads();
    if (threadIdx.x == 0) {
        float t = 0.0f;
        for (int i = 0; i < (int)(blockDim.x >> 5); ++i) t += ws[i];
        outp[row] = t;
    }
}

__global__ void group_kernel(const int* __restrict__ labels) {
    int i = blockIdx.x * blockDim.x + threadIdx.x;
    if (i < N_) {
        int c = labels[i];
        int s = atomicAdd(&g_cnt[c], 1);
        g_group[c * N_ + s] = i;
    }
}

// ---------------- tensor-core dist kernel ----------------
// stage tile layout (per 64KB stage): Bh @0, Bl @16K, Ah @32K, Al @48K
// each tile: 128 rows x 64 bf16 (128B/row), chunk swizzle: (c ^ (r&7))*16
__device__ __forceinline__ void stage_load(uint32_t sstage, int k0, int bi0, int aj0, int tid) {
    const __nv_bfloat16* srcs[4] = {g_bhi, g_blo, g_ahi, g_alo};
    const int r0s[4] = {bi0, bi0, aj0, aj0};
#pragma unroll
    for (int t = 0; t < 4; ++t) {
        const char* src = (const char*)srcs[t];
        uint32_t tb = sstage + t * TILE_BYTES;
#pragma unroll
        for (int q = 0; q < 4; ++q) {
            int linear = tid * 4 + q;           // 0..1023
            int r = linear >> 3, cch = linear & 7;
            const char* g = src + ((size_t)(r0s[t] + r) * F_ + k0 + cch * 8) * 2;
            uint32_t saddr = tb + (uint32_t)(r * 128) + (((uint32_t)(cch ^ (r & 7))) << 4);
            CP_ASYNC16(saddr, g);
        }
    }
}

__global__ __launch_bounds__(256)
void dist_kernel(const int* __restrict__ labels) {
    extern __shared__ char smem[];
    const uint32_t sbase = smem_u32(smem);
    const int tid = threadIdx.x;
    const int wid = tid >> 5;
    const int lane = tid & 31;
    const int bi0 = blockIdx.y * TM;     // b rows (i)
    const int aj0 = blockIdx.x * TNJ;    // a rows (j)
    const int wm = (wid & 1) * 64;       // warp row base in tile
    const int wn = (wid >> 1) * 32;      // warp col base in tile

    float acc[4][4][4];
#pragma unroll
    for (int am = 0; am < 4; ++am)
#pragma unroll
        for (int an = 0; an < 4; ++an)
#pragma unroll
            for (int x = 0; x < 4; ++x) acc[am][an][x] = 0.0f;

    stage_load(sbase, 0, bi0, aj0, tid);                 CP_COMMIT();
    stage_load(sbase + STAGE_BYTES, BK, bi0, aj0, tid);  CP_COMMIT();

    const int lr = lane & 15;     // ldmatrix row-within-16
    const int lh = lane >> 4;     // ldmatrix chunk select

    for (int c = 0; c < NSTAGE; ++c) {
        if (c < NSTAGE - 1) { CP_WAIT1(); } else { CP_WAIT0(); }
        __syncthreads();
        uint32_t sb = sbase + (uint32_t)(c & 1) * STAGE_BYTES;

#pragma unroll
        for (int ks = 0; ks < 4; ++ks) {
            uint32_t abh[4][4], abl[4][4], bah[2][4], bal[2][4];
#pragma unroll
            for (int am = 0; am < 4; ++am) {
                int row = wm + am * 16 + lr;
                uint32_t off = (uint32_t)(row * 128) +
                               (((uint32_t)((ks * 2 + lh) ^ (row & 7))) << 4);
                LDSM4(abh[am], sb + 0 * TILE_BYTES + off);
                LDSM4(abl[am], sb + 1 * TILE_BYTES + off);
            }
#pragma unroll
            for (int np = 0; np < 2; ++np) {
                int row = wn + np * 16 + lr;
                uint32_t off = (uint32_t)(row * 128) +
                               (((uint32_t)((ks * 2 + lh) ^ (row & 7))) << 4);
                LDSM4(bah[np], sb + 2 * TILE_BYTES + off);
                LDSM4(bal[np], sb + 3 * TILE_BYTES + off);
            }
#pragma unroll
            for (int am = 0; am < 4; ++am)
#pragma unroll
                for (int an = 0; an < 4; ++an) {
                    uint32_t h0 = bah[an >> 1][an & 1], h1 = bah[an >> 1][(an & 1) + 2];
                    uint32_t l0 = bal[an >> 1][an & 1], l1 = bal[an >> 1][(an & 1) + 2];
                    MMA16816(acc[am][an], abh[am], h0, h1);   // bh . ah
                    MMA16816(acc[am][an], abh[am], l0, l1);   // bh . al
                    MMA16816(acc[am][an], abl[am], h0, h1);   // bl . ah
                }
        }

        if (c + 2 < NSTAGE) {
            __syncthreads();
            stage_load(sbase + (uint32_t)(c & 1) * STAGE_BYTES, (c + 2) * BK, bi0, aj0, tid);
            CP_COMMIT();
        }
    }

    // ---------------- epilogue ----------------
    const int lrow2 = lane >> 2;          // 0..7
    const int lcol = (lane & 3) * 2;      // 0,2,4,6

    // column-side values (shared across m-atoms)
    float a2c[4][2];
    int lac[4][2];
#pragma unroll
    for (int an = 0; an < 4; ++an) {
        int gj = aj0 + wn + an * 8 + lcol;
        a2c[an][0] = g_a2[gj];     a2c[an][1] = g_a2[gj + 1];
        lac[an][0] = labels[gj];   lac[an][1] = labels[gj + 1];
    }

#pragma unroll
    for (int am = 0; am < 4; ++am) {
        int r0 = bi0 + wm + am * 16 + lrow2;     // row for d0,d1
        int r1 = r0 + 8;                          // row for d2,d3
        float b20 = g_b2[r0], b21 = g_b2[r1];
        int lb0 = labels[r0], lb1 = labels[r1];
        float n0 = 0.0f, n1 = 0.0f;
#pragma unroll
        for (int an = 0; an < 4; ++an) {
            int gj = aj0 + wn + an * 8 + lcol;
            float d00, d01, d10, d11;
            {
                float dsq = b20 + a2c[an][0] - 2.0f * acc[am][an][0];
                d00 = sqrtf(fmaxf(dsq, 0.0f));
                if (lac[an][0] != lb0) n0 += expf(1.0f - d00);
            }
            {
                float dsq = b20 + a2c[an][1] - 2.0f * acc[am][an][1];
                d01 = sqrtf(fmaxf(dsq, 0.0f));
                if (lac[an][1] != lb0) n0 += expf(1.0f - d01);
            }
            {
                float dsq = b21 + a2c[an][0] - 2.0f * acc[am][an][2];
                d10 = sqrtf(fmaxf(dsq, 0.0f));
                if (lac[an][0] != lb1) n1 += expf(1.0f - d10);
            }
            {
                float dsq = b21 + a2c[an][1] - 2.0f * acc[am][an][3];
                d11 = sqrtf(fmaxf(dsq, 0.0f));
                if (lac[an][1] != lb1) n1 += expf(1.0f - d11);
            }
            *(float2*)(g_D + (size_t)r0 * N_ + gj) = make_float2(d00, d01);
            *(float2*)(g_D + (size_t)r1 * N_ + gj) = make_float2(d10, d11);
        }
        // reduce across the 4 lanes sharing each row (lane&3 varies)
        n0 += __shfl_xor_sync(0xffffffffu, n0, 1);
        n0 += __shfl_xor_sync(0xffffffffu, n0, 2);
        n1 += __shfl_xor_sync(0xffffffffu, n1, 1);
        n1 += __shfl_xor_sync(0xffffffffu, n1, 2);
        if ((lane & 3) == 0) {
            atomicAdd(&g_negsum[r0], n0);
            atomicAdd(&g_negsum[r1], n1);
        }
    }
}

// positives-only gathered loss
__global__ void loss_kernel(const int* __restrict__ labels) {
    int i = blockIdx.x;
    int li = labels[i];
    int n = g_cnt[li];
    float nsi = g_negsum[i];
    const float* Drow = g_D + (size_t)i * N_;
    const int* grp = g_group + li * N_;
    float acc = 0.0f;
    for (int t = threadIdx.x; t < n; t += blockDim.x) {
        int j = grp[t];
        if (j == i) continue;
        float Jv = logf(nsi + g_negsum[j]) + Drow[j];
        float h = fmaxf(Jv, 0.0f);
        acc += h * h;
    }
#pragma unroll
    for (int o = 16; o; o >>= 1) acc += __shfl_xor_sync(0xffffffffu, acc, o);
    __shared__ float fs[4];
    int lane = threadIdx.x & 31, w = threadIdx.x >> 5;
    if (lane == 0) fs[w] = acc;
    __syncthreads();
    if (threadIdx.x == 0) {
        float t = 0.0f;
        for (int k = 0; k < (int)(blockDim.x >> 5); ++k) t += fs[k];
        atomicAdd(&g_sum, (double)t);
    }
}

__global__ void finalize_kernel(float* out) {
    long long np = 0;
    for (int c = 0; c < 16; ++c) { long long n = g_cnt[c]; np += n * (n - 1); }
    out[0] = (float)(g_sum / (2.0 * (double)np));
}

extern "C" void kernel_launch(void* const* d_in, const int* in_sizes, int n_in,
                              void* d_out, int out_size) {
    const float* a = (const float*)d_in[0];
    const float* b = (const float*)d_in[1];
    const int* labels = (const int*)d_in[2];
    float* out = (float*)d_out;

    cudaFuncSetAttribute(dist_kernel, cudaFuncAttributeMaxDynamicSharedMemorySize, SMEM_TOTAL);

    init_kernel<<<(N_ + 255) / 256, 256>>>();
    convert_kernel<<<2 * (N_ * F_ / 4) / 256, 256>>>(a, b);
    norms_kernel<<<2 * N_, 128>>>(a, b);
    group_kernel<<<(N_ + 255) / 256, 256>>>(labels);
    dim3 grid(N_ / TNJ, N_ / TM);
    dist_kernel<<<grid, 256, SMEM_TOTAL>>>(labels);
    loss_kernel<<<N_, 128>>>(labels);
    finalize_kernel<<<1, 1>>>(out);
}

// round 5
// speedup vs baseline: 2.6139x; 1.5499x over previous
#include <cuda_runtime.h>
#include <cuda_fp16.h>
#include <cstdint>
#include <math.h>

#define N_ 4096
#define F_ 512
#define TM 128
#define TNJ 128
#define BK 64
#define NSTAGE (F_ / BK)        // 8
#define TILE_BYTES 16384        // 128 rows x 128B
#define STAGE_BYTES (3 * TILE_BYTES)   // Bh, Ah, Al
#define SMEM_TOTAL (2 * STAGE_BYTES)   // 98304 -> 2 CTAs/SM

// ---------------- scratch (__device__ globals; no allocs allowed) ----------------
__device__ float g_D[(size_t)N_ * N_];                       // 64 MB distances
__device__ __align__(16) __half g_ah[(size_t)N_ * F_];
__device__ __align__(16) __half g_al[(size_t)N_ * F_];
__device__ __align__(16) __half g_bh[(size_t)N_ * F_];
__device__ float g_negsum[N_];
__device__ float g_a2[N_], g_b2[N_];
__device__ int   g_cnt[16];
__device__ int   g_group[16 * N_];
__device__ double g_sum;

// ---------------- helpers ----------------
__device__ __forceinline__ uint32_t smem_u32(const void* p) {
    uint32_t r;
    asm("{ .reg .u64 t; cvta.to.shared.u64 t, %1; cvt.u32.u64 %0, t; }" : "=r"(r) : "l"(p));
    return r;
}

#define LDSM4(r, addr) \
    asm volatile("ldmatrix.sync.aligned.m8n8.x4.shared.b16 {%0,%1,%2,%3}, [%4];" \
                 : "=r"((r)[0]), "=r"((r)[1]), "=r"((r)[2]), "=r"((r)[3]) : "r"(addr))

#define MMA16816(d, a, b0, b1) \
    asm volatile("mma.sync.aligned.m16n8k16.row.col.f32.f16.f16.f32 " \
                 "{%0,%1,%2,%3}, {%4,%5,%6,%7}, {%8,%9}, {%0,%1,%2,%3};" \
                 : "+f"((d)[0]), "+f"((d)[1]), "+f"((d)[2]), "+f"((d)[3]) \
                 : "r"((a)[0]), "r"((a)[1]), "r"((a)[2]), "r"((a)[3]), "r"(b0), "r"(b1))

#define CP_ASYNC16(saddr, gptr) \
    asm volatile("cp.async.cg.shared.global [%0], [%1], 16;" :: "r"(saddr), "l"(gptr))
#define CP_COMMIT() asm volatile("cp.async.commit_group;" ::: "memory")
#define CP_WAIT1()  asm volatile("cp.async.wait_group 1;" ::: "memory")
#define CP_WAIT0()  asm volatile("cp.async.wait_group 0;" ::: "memory")

// ---------------- small kernels ----------------
__global__ void init_kernel() {
    int i = blockIdx.x * blockDim.x + threadIdx.x;
    if (i < N_) g_negsum[i] = 0.0f;
    if (i < 16) g_cnt[i] = 0;
    if (i == 0) g_sum = 0.0;
}

// a -> (ah, al) fp16 split;  b -> bh fp16
__global__ void convert_kernel(const float* __restrict__ a, const float* __restrict__ b) {
    const int PER = N_ * F_ / 4;
    int idx = blockIdx.x * blockDim.x + threadIdx.x;
    if (idx < PER) {
        float4 v = ((const float4*)a)[idx];
        float vs[4] = {v.x, v.y, v.z, v.w};
        unsigned short h[4], l[4];
#pragma unroll
        for (int q = 0; q < 4; ++q) {
            __half hb = __float2half(vs[q]);
            __half lb = __float2half(vs[q] - __half2float(hb));
            h[q] = __half_as_ushort(hb);
            l[q] = __half_as_ushort(lb);
        }
        ((uint2*)g_ah)[idx] = make_uint2(((uint32_t)h[1] << 16) | h[0],
                                         ((uint32_t)h[3] << 16) | h[2]);
        ((uint2*)g_al)[idx] = make_uint2(((uint32_t)l[1] << 16) | l[0],
                                         ((uint32_t)l[3] << 16) | l[2]);
    } else {
        int e = idx - PER;
        float4 v = ((const float4*)b)[e];
        float vs[4] = {v.x, v.y, v.z, v.w};
        unsigned short h[4];
#pragma unroll
        for (int q = 0; q < 4; ++q) h[q] = __half_as_ushort(__float2half(vs[q]));
        ((uint2*)g_bh)[e] = make_uint2(((uint32_t)h[1] << 16) | h[0],
                                       ((uint32_t)h[3] << 16) | h[2]);
    }
}

__global__ void norms_kernel(const float* __restrict__ a, const float* __restrict__ b) {
    int row = blockIdx.x & (N_ - 1);
    const float* m = (blockIdx.x < N_) ? a : b;
    float* outp = (blockIdx.x < N_) ? g_a2 : g_b2;
    const float* p = m + (size_t)row * F_;
    float s = 0.0f;
    for (int k = threadIdx.x; k < F_; k += blockDim.x) { float v = p[k]; s += v * v; }
#pragma unroll
    for (int o = 16; o; o >>= 1) s += __shfl_xor_sync(0xffffffffu, s, o);
    __shared__ float ws[4];
    int lane = threadIdx.x & 31, w = threadIdx.x >> 5;
    if (lane == 0) ws[w] = s;
    __syncthreads();
    if (threadIdx.x == 0) {
        float t = 0.0f;
        for (int i = 0; i < (int)(blockDim.x >> 5); ++i) t += ws[i];
        outp[row] = t;
    }
}

__global__ void group_kernel(const int* __restrict__ labels) {
    int i = blockIdx.x * blockDim.x + threadIdx.x;
    if (i < N_) {
        int c = labels[i];
        int s = atomicAdd(&g_cnt[c], 1);
        g_group[c * N_ + s] = i;
    }
}

// ---------------- tensor-core dist kernel ----------------
// stage layout: Bh @0, Ah @16K, Al @32K; tile = 128 rows x 64 fp16 (128B/row)
// swizzle: chunk (c ^ (r&7))*16
__device__ __forceinline__ void stage_load(uint32_t sstage, int k0, int bi0, int aj0, int tid) {
    const __half* srcs[3] = {g_bh, g_ah, g_al};
    const int r0s[3] = {bi0, aj0, aj0};
#pragma unroll
    for (int t = 0; t < 3; ++t) {
        const char* src = (const char*)srcs[t];
        uint32_t tb = sstage + t * TILE_BYTES;
#pragma unroll
        for (int q = 0; q < 4; ++q) {
            int linear = tid * 4 + q;           // 0..1023
            int r = linear >> 3, cch = linear & 7;
            const char* g = src + ((size_t)(r0s[t] + r) * F_ + k0 + cch * 8) * 2;
            uint32_t saddr = tb + (uint32_t)(r * 128) + (((uint32_t)(cch ^ (r & 7))) << 4);
            CP_ASYNC16(saddr, g);
        }
    }
}

__global__ __launch_bounds__(256, 2)
void dist_kernel(const int* __restrict__ labels) {
    extern __shared__ char smem[];
    const uint32_t sbase = smem_u32(smem);
    const int tid = threadIdx.x;
    const int wid = tid >> 5;
    const int lane = tid & 31;
    const int bi0 = blockIdx.y * TM;     // b rows (i)
    const int aj0 = blockIdx.x * TNJ;    // a rows (j)
    const int wm = (wid & 1) * 64;       // warp row base
    const int wn = (wid >> 1) * 32;      // warp col base

    float acc[4][4][4];
#pragma unroll
    for (int am = 0; am < 4; ++am)
#pragma unroll
        for (int an = 0; an < 4; ++an)
#pragma unroll
            for (int x = 0; x < 4; ++x) acc[am][an][x] = 0.0f;

    stage_load(sbase, 0, bi0, aj0, tid);                 CP_COMMIT();
    stage_load(sbase + STAGE_BYTES, BK, bi0, aj0, tid);  CP_COMMIT();

    const int lr = lane & 15;
    const int lh = lane >> 4;

    for (int c = 0; c < NSTAGE; ++c) {
        if (c < NSTAGE - 1) { CP_WAIT1(); } else { CP_WAIT0(); }
        __syncthreads();
        uint32_t sb = sbase + (uint32_t)(c & 1) * STAGE_BYTES;

#pragma unroll
        for (int ks = 0; ks < 4; ++ks) {
            uint32_t abh[4][4], bah[2][4], bal[2][4];
#pragma unroll
            for (int am = 0; am < 4; ++am) {
                int row = wm + am * 16 + lr;
                uint32_t off = (uint32_t)(row * 128) +
                               (((uint32_t)((ks * 2 + lh) ^ (row & 7))) << 4);
                LDSM4(abh[am], sb + 0 * TILE_BYTES + off);
            }
#pragma unroll
            for (int np = 0; np < 2; ++np) {
                int row = wn + np * 16 + lr;
                uint32_t off = (uint32_t)(row * 128) +
                               (((uint32_t)((ks * 2 + lh) ^ (row & 7))) << 4);
                LDSM4(bah[np], sb + 1 * TILE_BYTES + off);
                LDSM4(bal[np], sb + 2 * TILE_BYTES + off);
            }
#pragma unroll
            for (int am = 0; am < 4; ++am)
#pragma unroll
                for (int an = 0; an < 4; ++an) {
                    uint32_t h0 = bah[an >> 1][an & 1], h1 = bah[an >> 1][(an & 1) + 2];
                    uint32_t l0 = bal[an >> 1][an & 1], l1 = bal[an >> 1][(an & 1) + 2];
                    MMA16816(acc[am][an], abh[am], h0, h1);   // bh . ah
                    MMA16816(acc[am][an], abh[am], l0, l1);   // bh . al
                }
        }

        if (c + 2 < NSTAGE) {
            __syncthreads();
            stage_load(sbase + (uint32_t)(c & 1) * STAGE_BYTES, (c + 2) * BK, bi0, aj0, tid);
            CP_COMMIT();
        }
    }

    // ---------------- epilogue ----------------
    const int lrow2 = lane >> 2;
    const int lcol = (lane & 3) * 2;

    float a2c[4][2];
    int lac[4][2];
#pragma unroll
    for (int an = 0; an < 4; ++an) {
        int gj = aj0 + wn + an * 8 + lcol;
        a2c[an][0] = g_a2[gj];     a2c[an][1] = g_a2[gj + 1];
        lac[an][0] = labels[gj];   lac[an][1] = labels[gj + 1];
    }

#pragma unroll
    for (int am = 0; am < 4; ++am) {
        int r0 = bi0 + wm + am * 16 + lrow2;
        int r1 = r0 + 8;
        float b20 = g_b2[r0], b21 = g_b2[r1];
        int lb0 = labels[r0], lb1 = labels[r1];
        float n0 = 0.0f, n1 = 0.0f;
#pragma unroll
        for (int an = 0; an < 4; ++an) {
            int gj = aj0 + wn + an * 8 + lcol;
            float d00, d01, d10, d11;
            {
                float dsq = b20 + a2c[an][0] - 2.0f * acc[am][an][0];
                d00 = sqrtf(fmaxf(dsq, 0.0f));
                if (lac[an][0] != lb0) n0 += expf(1.0f - d00);
            }
            {
                float dsq = b20 + a2c[an][1] - 2.0f * acc[am][an][1];
                d01 = sqrtf(fmaxf(dsq, 0.0f));
                if (lac[an][1] != lb0) n0 += expf(1.0f - d01);
            }
            {
                float dsq = b21 + a2c[an][0] - 2.0f * acc[am][an][2];
                d10 = sqrtf(fmaxf(dsq, 0.0f));
                if (lac[an][0] != lb1) n1 += expf(1.0f - d10);
            }
            {
                float dsq = b21 + a2c[an][1] - 2.0f * acc[am][an][3];
                d11 = sqrtf(fmaxf(dsq, 0.0f));
                if (lac[an][1] != lb1) n1 += expf(1.0f - d11);
            }
            *(float2*)(g_D + (size_t)r0 * N_ + gj) = make_float2(d00, d01);
            *(float2*)(g_D + (size_t)r1 * N_ + gj) = make_float2(d10, d11);
        }
        n0 += __shfl_xor_sync(0xffffffffu, n0, 1);
        n0 += __shfl_xor_sync(0xffffffffu, n0, 2);
        n1 += __shfl_xor_sync(0xffffffffu, n1, 1);
        n1 += __shfl_xor_sync(0xffffffffu, n1, 2);
        if ((lane & 3) == 0) {
            atomicAdd(&g_negsum[r0], n0);
            atomicAdd(&g_negsum[r1], n1);
        }
    }
}

// positives-only gathered loss
__global__ void loss_kernel(const int* __restrict__ labels) {
    int i = blockIdx.x;
    int li = labels[i];
    int n = g_cnt[li];
    float nsi = g_negsum[i];
    const float* Drow = g_D + (size_t)i * N_;
    const int* grp = g_group + li * N_;
    float acc = 0.0f;
    for (int t = threadIdx.x; t < n; t += blockDim.x) {
        int j = grp[t];
        if (j == i) continue;
        float Jv = logf(nsi + g_negsum[j]) + Drow[j];
        float h = fmaxf(Jv, 0.0f);
        acc += h * h;
    }
#pragma unroll
    for (int o = 16; o; o >>= 1) acc += __shfl_xor_sync(0xffffffffu, acc, o);
    __shared__ float fs[4];
    int lane = threadIdx.x & 31, w = threadIdx.x >> 5;
    if (lane == 0) fs[w] = acc;
    __syncthreads();
    if (threadIdx.x == 0) {
        float t = 0.0f;
        for (int k = 0; k < (int)(blockDim.x >> 5); ++k) t += fs[k];
        atomicAdd(&g_sum, (double)t);
    }
}

__global__ void finalize_kernel(float* out) {
    long long np = 0;
    for (int c = 0; c < 16; ++c) { long long n = g_cnt[c]; np += n * (n - 1); }
    out[0] = (float)(g_sum / (2.0 * (double)np));
}

extern "C" void kernel_launch(void* const* d_in, const int* in_sizes, int n_in,
                              void* d_out, int out_size) {
    const float* a = (const float*)d_in[0];
    const float* b = (const float*)d_in[1];
    const int* labels = (const int*)d_in[2];
    float* out = (float*)d_out;

    cudaFuncSetAttribute(dist_kernel, cudaFuncAttributeMaxDynamicSharedMemorySize, SMEM_TOTAL);

    init_kernel<<<(N_ + 255) / 256, 256>>>();
    convert_kernel<<<2 * (N_ * F_ / 4) / 256, 256>>>(a, b);
    norms_kernel<<<2 * N_, 128>>>(a, b);
    group_kernel<<<(N_ + 255) / 256, 256>>>(labels);
    dim3 grid(N_ / TNJ, N_ / TM);
    dist_kernel<<<grid, 256, SMEM_TOTAL>>>(labels);
    loss_kernel<<<N_, 128>>>(labels);
    finalize_kernel<<<1, 1>>>(out);
}

// round 6
// speedup vs baseline: 3.6478x; 1.3955x over previous
#include <cuda_runtime.h>
#include <cuda_fp16.h>
#include <cstdint>
#include <math.h>

#define N_ 4096
#define F_ 512
#define TM 128
#define TNJ 128
#define BK 64
#define NSTAGE (F_ / BK)        // 8
#define TILE_BYTES 16384        // 128 rows x 128B
#define STAGE_BYTES (2 * TILE_BYTES)   // Bh, Ah
#define SMEM_TOTAL (2 * STAGE_BYTES)   // 65536

// ---------------- scratch (__device__ globals; no allocs allowed) ----------------
__device__ float g_D[(size_t)N_ * N_];                       // 64 MB distances
__device__ __align__(16) __half g_ah[(size_t)N_ * F_];
__device__ __align__(16) __half g_bh[(size_t)N_ * F_];
__device__ float g_negsum[N_];
__device__ float g_a2[N_], g_b2[N_];
__device__ int   g_cnt[16];
__device__ int   g_group[16 * N_];
__device__ double g_sum;

// ---------------- helpers ----------------
__device__ __forceinline__ uint32_t smem_u32(const void* p) {
    uint32_t r;
    asm("{ .reg .u64 t; cvta.to.shared.u64 t, %1; cvt.u32.u64 %0, t; }" : "=r"(r) : "l"(p));
    return r;
}

#define LDSM4(r, addr) \
    asm volatile("ldmatrix.sync.aligned.m8n8.x4.shared.b16 {%0,%1,%2,%3}, [%4];" \
                 : "=r"((r)[0]), "=r"((r)[1]), "=r"((r)[2]), "=r"((r)[3]) : "r"(addr))

#define MMA16816(d, a, b0, b1) \
    asm volatile("mma.sync.aligned.m16n8k16.row.col.f32.f16.f16.f32 " \
                 "{%0,%1,%2,%3}, {%4,%5,%6,%7}, {%8,%9}, {%0,%1,%2,%3};" \
                 : "+f"((d)[0]), "+f"((d)[1]), "+f"((d)[2]), "+f"((d)[3]) \
                 : "r"((a)[0]), "r"((a)[1]), "r"((a)[2]), "r"((a)[3]), "r"(b0), "r"(b1))

#define CP_ASYNC16(saddr, gptr) \
    asm volatile("cp.async.cg.shared.global [%0], [%1], 16;" :: "r"(saddr), "l"(gptr))
#define CP_COMMIT() asm volatile("cp.async.commit_group;" ::: "memory")
#define CP_WAIT1()  asm volatile("cp.async.wait_group 1;" ::: "memory")
#define CP_WAIT0()  asm volatile("cp.async.wait_group 0;" ::: "memory")

// ---------------- small kernels ----------------
__global__ void init_kernel() {
    int i = blockIdx.x * blockDim.x + threadIdx.x;
    if (i < N_) g_negsum[i] = 0.0f;
    if (i < 16) g_cnt[i] = 0;
    if (i == 0) g_sum = 0.0;
}

// fp32 -> fp16 for both matrices
__global__ void convert_kernel(const float* __restrict__ a, const float* __restrict__ b) {
    const int PER = N_ * F_ / 4;
    int idx = blockIdx.x * blockDim.x + threadIdx.x;
    const float* src;
    __half* dst;
    int e;
    if (idx < PER) { src = a; dst = g_ah; e = idx; }
    else           { src = b; dst = g_bh; e = idx - PER; }
    float4 v = ((const float4*)src)[e];
    float vs[4] = {v.x, v.y, v.z, v.w};
    unsigned short h[4];
#pragma unroll
    for (int q = 0; q < 4; ++q) h[q] = __half_as_ushort(__float2half(vs[q]));
    ((uint2*)dst)[e] = make_uint2(((uint32_t)h[1] << 16) | h[0],
                                  ((uint32_t)h[3] << 16) | h[2]);
}

__global__ void norms_kernel(const float* __restrict__ a, const float* __restrict__ b) {
    int row = blockIdx.x & (N_ - 1);
    const float* m = (blockIdx.x < N_) ? a : b;
    float* outp = (blockIdx.x < N_) ? g_a2 : g_b2;
    const float* p = m + (size_t)row * F_;
    float s = 0.0f;
    for (int k = threadIdx.x; k < F_; k += blockDim.x) { float v = p[k]; s += v * v; }
#pragma unroll
    for (int o = 16; o; o >>= 1) s += __shfl_xor_sync(0xffffffffu, s, o);
    __shared__ float ws[4];
    int lane = threadIdx.x & 31, w = threadIdx.x >> 5;
    if (lane == 0) ws[w] = s;
    __syncthreads();
    if (threadIdx.x == 0) {
        float t = 0.0f;
        for (int i = 0; i < (int)(blockDim.x >> 5); ++i) t += ws[i];
        outp[row] = t;
    }
}

__global__ void group_kernel(const int* __restrict__ labels) {
    int i = blockIdx.x * blockDim.x + threadIdx.x;
    if (i < N_) {
        int c = labels[i];
        int s = atomicAdd(&g_cnt[c], 1);
        g_group[c * N_ + s] = i;
    }
}

// ---------------- tensor-core dist kernel ----------------
// stage layout: Bh @0, Ah @16K; tile = 128 rows x 64 fp16 (128B/row)
// swizzle: chunk (c ^ (r&7))*16
__device__ __forceinline__ void stage_load(uint32_t sstage, int k0, int bi0, int aj0, int tid) {
    const __half* srcs[2] = {g_bh, g_ah};
    const int r0s[2] = {bi0, aj0};
#pragma unroll
    for (int t = 0; t < 2; ++t) {
        const char* src = (const char*)srcs[t];
        uint32_t tb = sstage + t * TILE_BYTES;
#pragma unroll
        for (int q = 0; q < 4; ++q) {
            int linear = tid * 4 + q;           // 0..1023
            int r = linear >> 3, cch = linear & 7;
            const char* g = src + ((size_t)(r0s[t] + r) * F_ + k0 + cch * 8) * 2;
            uint32_t saddr = tb + (uint32_t)(r * 128) + (((uint32_t)(cch ^ (r & 7))) << 4);
            CP_ASYNC16(saddr, g);
        }
    }
}

__global__ __launch_bounds__(256, 2)
void dist_kernel(const int* __restrict__ labels) {
    extern __shared__ char smem[];
    const uint32_t sbase = smem_u32(smem);
    const int tid = threadIdx.x;
    const int wid = tid >> 5;
    const int lane = tid & 31;
    const int bi0 = blockIdx.y * TM;     // b rows (i)
    const int aj0 = blockIdx.x * TNJ;    // a rows (j)
    const int wm = (wid & 1) * 64;       // warp row base
    const int wn = (wid >> 1) * 32;      // warp col base

    float acc[4][4][4];
#pragma unroll
    for (int am = 0; am < 4; ++am)
#pragma unroll
        for (int an = 0; an < 4; ++an)
#pragma unroll
            for (int x = 0; x < 4; ++x) acc[am][an][x] = 0.0f;

    stage_load(sbase, 0, bi0, aj0, tid);                 CP_COMMIT();
    stage_load(sbase + STAGE_BYTES, BK, bi0, aj0, tid);  CP_COMMIT();

    const int lr = lane & 15;
    const int lh = lane >> 4;

    for (int c = 0; c < NSTAGE; ++c) {
        if (c < NSTAGE - 1) { CP_WAIT1(); } else { CP_WAIT0(); }
        __syncthreads();
        uint32_t sb = sbase + (uint32_t)(c & 1) * STAGE_BYTES;

#pragma unroll
        for (int ks = 0; ks < 4; ++ks) {
            uint32_t abh[4][4], bah[2][4];
#pragma unroll
            for (int am = 0; am < 4; ++am) {
                int row = wm + am * 16 + lr;
                uint32_t off = (uint32_t)(row * 128) +
                               (((uint32_t)((ks * 2 + lh) ^ (row & 7))) << 4);
                LDSM4(abh[am], sb + 0 * TILE_BYTES + off);
            }
#pragma unroll
            for (int np = 0; np < 2; ++np) {
                int row = wn + np * 16 + lr;
                uint32_t off = (uint32_t)(row * 128) +
                               (((uint32_t)((ks * 2 + lh) ^ (row & 7))) << 4);
                LDSM4(bah[np], sb + 1 * TILE_BYTES + off);
            }
#pragma unroll
            for (int am = 0; am < 4; ++am)
#pragma unroll
                for (int an = 0; an < 4; ++an) {
                    uint32_t h0 = bah[an >> 1][an & 1], h1 = bah[an >> 1][(an & 1) + 2];
                    MMA16816(acc[am][an], abh[am], h0, h1);   // bh . ah
                }
        }

        if (c + 2 < NSTAGE) {
            __syncthreads();
            stage_load(sbase + (uint32_t)(c & 1) * STAGE_BYTES, (c + 2) * BK, bi0, aj0, tid);
            CP_COMMIT();
        }
    }

    // ---------------- epilogue ----------------
    const int lrow2 = lane >> 2;
    const int lcol = (lane & 3) * 2;

    float a2c[4][2];
    int lac[4][2];
#pragma unroll
    for (int an = 0; an < 4; ++an) {
        int gj = aj0 + wn + an * 8 + lcol;
        a2c[an][0] = g_a2[gj];     a2c[an][1] = g_a2[gj + 1];
        lac[an][0] = labels[gj];   lac[an][1] = labels[gj + 1];
    }

#pragma unroll
    for (int am = 0; am < 4; ++am) {
        int r0 = bi0 + wm + am * 16 + lrow2;
        int r1 = r0 + 8;
        float b20 = g_b2[r0], b21 = g_b2[r1];
        int lb0 = labels[r0], lb1 = labels[r1];
        float n0 = 0.0f, n1 = 0.0f;
#pragma unroll
        for (int an = 0; an < 4; ++an) {
            int gj = aj0 + wn + an * 8 + lcol;
            float d00, d01, d10, d11;
            {
                float dsq = b20 + a2c[an][0] - 2.0f * acc[am][an][0];
                d00 = sqrtf(fmaxf(dsq, 0.0f));
                if (lac[an][0] != lb0) n0 += expf(1.0f - d00);
            }
            {
                float dsq = b20 + a2c[an][1] - 2.0f * acc[am][an][1];
                d01 = sqrtf(fmaxf(dsq, 0.0f));
                if (lac[an][1] != lb0) n0 += expf(1.0f - d01);
            }
            {
                float dsq = b21 + a2c[an][0] - 2.0f * acc[am][an][2];
                d10 = sqrtf(fmaxf(dsq, 0.0f));
                if (lac[an][0] != lb1) n1 += expf(1.0f - d10);
            }
            {
                float dsq = b21 + a2c[an][1] - 2.0f * acc[am][an][3];
                d11 = sqrtf(fmaxf(dsq, 0.0f));
                if (lac[an][1] != lb1) n1 += expf(1.0f - d11);
            }
            *(float2*)(g_D + (size_t)r0 * N_ + gj) = make_float2(d00, d01);
            *(float2*)(g_D + (size_t)r1 * N_ + gj) = make_float2(d10, d11);
        }
        n0 += __shfl_xor_sync(0xffffffffu, n0, 1);
        n0 += __shfl_xor_sync(0xffffffffu, n0, 2);
        n1 += __shfl_xor_sync(0xffffffffu, n1, 1);
        n1 += __shfl_xor_sync(0xffffffffu, n1, 2);
        if ((lane & 3) == 0) {
            atomicAdd(&g_negsum[r0], n0);
            atomicAdd(&g_negsum[r1], n1);
        }
    }
}

// positives-only gathered loss
__global__ void loss_kernel(const int* __restrict__ labels) {
    int i = blockIdx.x;
    int li = labels[i];
    int n = g_cnt[li];
    float nsi = g_negsum[i];
    const float* Drow = g_D + (size_t)i * N_;
    const int* grp = g_group + li * N_;
    float acc = 0.0f;
    for (int t = threadIdx.x; t < n; t += blockDim.x) {
        int j = grp[t];
        if (j == i) continue;
        float Jv = logf(nsi + g_negsum[j]) + Drow[j];
        float h = fmaxf(Jv, 0.0f);
        acc += h * h;
    }
#pragma unroll
    for (int o = 16; o; o >>= 1) acc += __shfl_xor_sync(0xffffffffu, acc, o);
    __shared__ float fs[4];
    int lane = threadIdx.x & 31, w = threadIdx.x >> 5;
    if (lane == 0) fs[w] = acc;
    __syncthreads();
    if (threadIdx.x == 0) {
        float t = 0.0f;
        for (int k = 0; k < (int)(blockDim.x >> 5); ++k) t += fs[k];
        atomicAdd(&g_sum, (double)t);
    }
}

__global__ void finalize_kernel(float* out) {
    long long np = 0;
    for (int c = 0; c < 16; ++c) { long long n = g_cnt[c]; np += n * (n - 1); }
    out[0] = (float)(g_sum / (2.0 * (double)np));
}

extern "C" void kernel_launch(void* const* d_in, const int* in_sizes, int n_in,
                              void* d_out, int out_size) {
    const float* a = (const float*)d_in[0];
    const float* b = (const float*)d_in[1];
    const int* labels = (const int*)d_in[2];
    float* out = (float*)d_out;

    cudaFuncSetAttribute(dist_kernel, cudaFuncAttributeMaxDynamicSharedMemorySize, SMEM_TOTAL);

    init_kernel<<<(N_ + 255) / 256, 256>>>();
    convert_kernel<<<2 * (N_ * F_ / 4) / 256, 256>>>(a, b);
    norms_kernel<<<2 * N_, 128>>>(a, b);
    group_kernel<<<(N_ + 255) / 256, 256>>>(labels);
    dim3 grid(N_ / TNJ, N_ / TM);
    dist_kernel<<<grid, 256, SMEM_TOTAL>>>(labels);
    loss_kernel<<<N_, 128>>>(labels);
    finalize_kernel<<<1, 1>>>(out);
}

// round 7
// speedup vs baseline: 4.3506x; 1.1927x over previous
#include <cuda_runtime.h>
#include <cuda_fp16.h>
#include <cstdint>
#include <math.h>

#define N_ 4096
#define F_ 512
#define TM 128
#define TNJ 128
#define BK 64
#define NCH (F_ / BK)            // 8 k-chunks
#define TILE_BYTES 16384         // 128 rows x 128B
#define STAGE_BYTES (2 * TILE_BYTES)   // Bh tile + Ah tile = 32KB
#define SMEM_TOTAL (3 * STAGE_BYTES)   // 98304, 2 CTAs/SM

// ---------------- scratch ----------------
__device__ float g_D[(size_t)N_ * N_];
__device__ __align__(16) __half g_ah[(size_t)N_ * F_];
__device__ __align__(16) __half g_bh[(size_t)N_ * F_];
__device__ float g_negsum[N_];
__device__ float g_a2[N_], g_b2[N_];
__device__ int   g_cnt[16];
__device__ int   g_group[16 * N_];
__device__ double g_sum;

// ---------------- helpers ----------------
__device__ __forceinline__ uint32_t smem_u32(const void* p) {
    uint32_t r;
    asm("{ .reg .u64 t; cvta.to.shared.u64 t, %1; cvt.u32.u64 %0, t; }" : "=r"(r) : "l"(p));
    return r;
}
__device__ __forceinline__ float fsqrt_ap(float x) {
    float r; asm("sqrt.approx.f32 %0, %1;" : "=f"(r) : "f"(x)); return r;
}

#define LDSM4(r, addr) \
    asm volatile("ldmatrix.sync.aligned.m8n8.x4.shared.b16 {%0,%1,%2,%3}, [%4];" \
                 : "=r"((r)[0]), "=r"((r)[1]), "=r"((r)[2]), "=r"((r)[3]) : "r"(addr))

#define MMA16816(d, a, b0, b1) \
    asm volatile("mma.sync.aligned.m16n8k16.row.col.f32.f16.f16.f32 " \
                 "{%0,%1,%2,%3}, {%4,%5,%6,%7}, {%8,%9}, {%0,%1,%2,%3};" \
                 : "+f"((d)[0]), "+f"((d)[1]), "+f"((d)[2]), "+f"((d)[3]) \
                 : "r"((a)[0]), "r"((a)[1]), "r"((a)[2]), "r"((a)[3]), "r"(b0), "r"(b1))

#define CP_ASYNC16(saddr, gptr) \
    asm volatile("cp.async.cg.shared.global [%0], [%1], 16;" :: "r"(saddr), "l"(gptr))
#define CP_COMMIT() asm volatile("cp.async.commit_group;" ::: "memory")
#define CP_WAIT1()  asm volatile("cp.async.wait_group 1;" ::: "memory")
#define CP_WAIT0()  asm volatile("cp.async.wait_group 0;" ::: "memory")

// ---------------- prep: convert fp32->fp16, row norms, negsum init ----------------
// grid 2*N_ blocks x 128 threads; block r<N_ handles a-row r, else b-row
__global__ void prep_kernel(const float* __restrict__ a, const float* __restrict__ b) {
    int r = blockIdx.x & (N_ - 1);
    bool isA = blockIdx.x < N_;
    const float* src = (isA ? a : b) + (size_t)r * F_;
    int tid = threadIdx.x;

    float4 v = ((const float4*)src)[tid];
    unsigned short h[4];
    h[0] = __half_as_ushort(__float2half(v.x));
    h[1] = __half_as_ushort(__float2half(v.y));
    h[2] = __half_as_ushort(__float2half(v.z));
    h[3] = __half_as_ushort(__float2half(v.w));
    ((uint2*)(isA ? g_ah : g_bh))[r * (F_ / 4) + tid] =
        make_uint2(((uint32_t)h[1] << 16) | h[0], ((uint32_t)h[3] << 16) | h[2]);

    float s = v.x * v.x + v.y * v.y + v.z * v.z + v.w * v.w;
#pragma unroll
    for (int o = 16; o; o >>= 1) s += __shfl_xor_sync(0xffffffffu, s, o);
    __shared__ float ws[4];
    int lane = tid & 31, w = tid >> 5;
    if (lane == 0) ws[w] = s;
    __syncthreads();
    if (tid == 0) {
        float t = ws[0] + ws[1] + ws[2] + ws[3];
        (isA ? g_a2 : g_b2)[r] = t;
        if (isA) g_negsum[r] = 0.0f;
    }
}

// single block: label grouping + counters + g_sum init
__global__ void group_kernel(const int* __restrict__ labels) {
    __shared__ int sc[16];
    int tid = threadIdx.x;
    if (tid < 16) sc[tid] = 0;
    if (tid == 0) g_sum = 0.0;
    __syncthreads();
    for (int e = tid; e < N_; e += blockDim.x) {
        int c = labels[e];
        int s = atomicAdd(&sc[c], 1);
        g_group[c * N_ + s] = e;
    }
    __syncthreads();
    if (tid < 16) g_cnt[tid] = sc[tid];
}

// ---------------- dist kernel: 3-stage pipelined fp16 HMMA ----------------
__device__ __forceinline__ void load_stage(uint32_t sb, uint32_t koff,
                                           const char* baseB, const char* baseA,
                                           const uint32_t* goff, const uint32_t* smoff) {
#pragma unroll
    for (int k = 0; k < 4; ++k) CP_ASYNC16(sb + smoff[k], baseB + goff[k] + koff);
#pragma unroll
    for (int k = 4; k < 8; ++k) CP_ASYNC16(sb + smoff[k], baseA + goff[k] + koff);
}

__global__ __launch_bounds__(256, 2)
void dist_kernel(const int* __restrict__ labels) {
    extern __shared__ char smem[];
    const uint32_t sbase = smem_u32(smem);
    const int tid = threadIdx.x;
    const int wid = tid >> 5;
    const int lane = tid & 31;
    const int bi0 = blockIdx.y * TM;
    const int aj0 = blockIdx.x * TNJ;
    const int wm = (wid & 1) * 64;
    const int wn = (wid >> 1) * 32;

    // hoisted load addressing (32-bit offsets, bytes)
    uint32_t goff[8], smoff[8];
#pragma unroll
    for (int t = 0; t < 2; ++t)
#pragma unroll
        for (int q = 0; q < 4; ++q) {
            int linear = tid * 4 + q;
            int r = linear >> 3, cch = linear & 7;
            int row = (t ? aj0 : bi0) + r;
            goff[t * 4 + q] = (uint32_t)(row * (F_ * 2) + cch * 16);
            smoff[t * 4 + q] = (uint32_t)(t * TILE_BYTES + r * 128 +
                                          ((cch ^ (r & 7)) << 4));
        }
    const char* baseB = (const char*)g_bh;
    const char* baseA = (const char*)g_ah;

    float acc[4][4][4];
#pragma unroll
    for (int am = 0; am < 4; ++am)
#pragma unroll
        for (int an = 0; an < 4; ++an)
#pragma unroll
            for (int x = 0; x < 4; ++x) acc[am][an][x] = 0.0f;

    load_stage(sbase, 0, baseB, baseA, goff, smoff);               CP_COMMIT();
    load_stage(sbase + STAGE_BYTES, 128, baseB, baseA, goff, smoff); CP_COMMIT();

    const int lr = lane & 15;
    const int lh = lane >> 4;

#pragma unroll
    for (int c = 0; c < NCH; ++c) {
        if (c < NCH - 1) { CP_WAIT1(); } else { CP_WAIT0(); }
        __syncthreads();
        if (c + 2 < NCH) {
            load_stage(sbase + (uint32_t)((c + 2) % 3) * STAGE_BYTES,
                       (uint32_t)(c + 2) * 128, baseB, baseA, goff, smoff);
            CP_COMMIT();
        }
        uint32_t sb = sbase + (uint32_t)(c % 3) * STAGE_BYTES;

#pragma unroll
        for (int ks = 0; ks < 4; ++ks) {
            uint32_t abh[4][4], bah[2][4];
#pragma unroll
            for (int am = 0; am < 4; ++am) {
                int row = wm + am * 16 + lr;
                uint32_t off = (uint32_t)(row * 128) +
                               (((uint32_t)((ks * 2 + lh) ^ (row & 7))) << 4);
                LDSM4(abh[am], sb + off);
            }
#pragma unroll
            for (int np = 0; np < 2; ++np) {
                int row = wn + np * 16 + lr;
                uint32_t off = (uint32_t)(row * 128) +
                               (((uint32_t)((ks * 2 + lh) ^ (row & 7))) << 4);
                LDSM4(bah[np], sb + TILE_BYTES + off);
            }
#pragma unroll
            for (int am = 0; am < 4; ++am)
#pragma unroll
                for (int an = 0; an < 4; ++an) {
                    uint32_t h0 = bah[an >> 1][an & 1], h1 = bah[an >> 1][(an & 1) + 2];
                    MMA16816(acc[am][an], abh[am], h0, h1);
                }
        }
    }

    // ---------------- epilogue ----------------
    const int lrow2 = lane >> 2;
    const int lcol = (lane & 3) * 2;

    float a2c[4][2];
    int lac[4][2];
#pragma unroll
    for (int an = 0; an < 4; ++an) {
        int gj = aj0 + wn + an * 8 + lcol;
        a2c[an][0] = g_a2[gj];     a2c[an][1] = g_a2[gj + 1];
        lac[an][0] = labels[gj];   lac[an][1] = labels[gj + 1];
    }

#pragma unroll
    for (int am = 0; am < 4; ++am) {
        int r0 = bi0 + wm + am * 16 + lrow2;
        int r1 = r0 + 8;
        float b20 = g_b2[r0], b21 = g_b2[r1];
        int lb0 = labels[r0], lb1 = labels[r1];
        float n0 = 0.0f, n1 = 0.0f;
#pragma unroll
        for (int an = 0; an < 4; ++an) {
            int gj = aj0 + wn + an * 8 + lcol;
            float d00 = fsqrt_ap(fmaxf(b20 + a2c[an][0] - 2.0f * acc[am][an][0], 0.0f));
            float d01 = fsqrt_ap(fmaxf(b20 + a2c[an][1] - 2.0f * acc[am][an][1], 0.0f));
            float d10 = fsqrt_ap(fmaxf(b21 + a2c[an][0] - 2.0f * acc[am][an][2], 0.0f));
            float d11 = fsqrt_ap(fmaxf(b21 + a2c[an][1] - 2.0f * acc[am][an][3], 0.0f));
            if (lac[an][0] != lb0) n0 += __expf(1.0f - d00);
            if (lac[an][1] != lb0) n0 += __expf(1.0f - d01);
            if (lac[an][0] != lb1) n1 += __expf(1.0f - d10);
            if (lac[an][1] != lb1) n1 += __expf(1.0f - d11);
            *(float2*)(g_D + (size_t)r0 * N_ + gj) = make_float2(d00, d01);
            *(float2*)(g_D + (size_t)r1 * N_ + gj) = make_float2(d10, d11);
        }
        n0 += __shfl_xor_sync(0xffffffffu, n0, 1);
        n0 += __shfl_xor_sync(0xffffffffu, n0, 2);
        n1 += __shfl_xor_sync(0xffffffffu, n1, 1);
        n1 += __shfl_xor_sync(0xffffffffu, n1, 2);
        if ((lane & 3) == 0) {
            atomicAdd(&g_negsum[r0], n0);
            atomicAdd(&g_negsum[r1], n1);
        }
    }
}

// positives-only gathered loss
__global__ void loss_kernel(const int* __restrict__ labels) {
    int i = blockIdx.x;
    int li = labels[i];
    int n = g_cnt[li];
    float nsi = g_negsum[i];
    const float* Drow = g_D + (size_t)i * N_;
    const int* grp = g_group + li * N_;
    float acc = 0.0f;
    for (int t = threadIdx.x; t < n; t += blockDim.x) {
        int j = grp[t];
        if (j == i) continue;
        float Jv = __logf(nsi + g_negsum[j]) + Drow[j];
        float h = fmaxf(Jv, 0.0f);
        acc += h * h;
    }
#pragma unroll
    for (int o = 16; o; o >>= 1) acc += __shfl_xor_sync(0xffffffffu, acc, o);
    __shared__ float fs[4];
    int lane = threadIdx.x & 31, w = threadIdx.x >> 5;
    if (lane == 0) fs[w] = acc;
    __syncthreads();
    if (threadIdx.x == 0) {
        float t = 0.0f;
        for (int k = 0; k < (int)(blockDim.x >> 5); ++k) t += fs[k];
        atomicAdd(&g_sum, (double)t);
    }
}

__global__ void finalize_kernel(float* out) {
    long long np = 0;
    for (int c = 0; c < 16; ++c) { long long n = g_cnt[c]; np += n * (n - 1); }
    out[0] = (float)(g_sum / (2.0 * (double)np));
}

extern "C" void kernel_launch(void* const* d_in, const int* in_sizes, int n_in,
                              void* d_out, int out_size) {
    const float* a = (const float*)d_in[0];
    const float* b = (const float*)d_in[1];
    const int* labels = (const int*)d_in[2];
    float* out = (float*)d_out;

    cudaFuncSetAttribute(dist_kernel, cudaFuncAttributeMaxDynamicSharedMemorySize, SMEM_TOTAL);

    prep_kernel<<<2 * N_, 128>>>(a, b);
    group_kernel<<<1, 1024>>>(labels);
    dim3 grid(N_ / TNJ, N_ / TM);
    dist_kernel<<<grid, 256, SMEM_TOTAL>>>(labels);
    loss_kernel<<<N_, 128>>>(labels);
    finalize_kernel<<<1, 1>>>(out);
}